// round 2
// baseline (speedup 1.0000x reference)
#include <cuda_runtime.h>
#include <math.h>

// Problem constants
#define Bn    8
#define En    64
#define Hn    256
#define Wn    256
#define Kn    8
#define NPOSn 4
#define HWn   (Hn*Wn)
#define CHUNK 2048
#define NCHUNK (HWn/CHUNK)        // 32 chunks per image
#define NBLK  (Bn*NCHUNK)         // 256 means-blocks
#define TEMPf 0.2f
#define EPSf  1e-8f

// Allocation-free scratch (__device__ globals)
__device__ float g_part[NBLK][Kn*En];   // per-block partial class sums (512 KB)
__device__ float g_cnt[NBLK][Kn];       // per-block partial counts
__device__ float g_partial[Bn];         // per-image loss partials

// ---------------------------------------------------------------------------
// packed f32x2 helpers (sm_103a)
// ---------------------------------------------------------------------------
__device__ __forceinline__ unsigned long long ffma2(unsigned long long a,
                                                    unsigned long long b,
                                                    unsigned long long c) {
    unsigned long long d;
    asm("fma.rn.f32x2 %0, %1, %2, %3;" : "=l"(d) : "l"(a), "l"(b), "l"(c));
    return d;
}
__device__ __forceinline__ unsigned long long pack2(float lo, float hi) {
    unsigned long long r;
    asm("mov.b64 %0, {%1, %2};" : "=l"(r) : "f"(lo), "f"(hi));
    return r;
}
__device__ __forceinline__ void unpack2(unsigned long long v, float& lo, float& hi) {
    asm("mov.b64 {%0, %1}, %2;" : "=f"(lo), "=f"(hi) : "l"(v));
}

// ---------------------------------------------------------------------------
// Kernel 1: class-sum partials. grid = 256 (8 images x 32 chunks), 256 thr.
// Memory-bound stage: reads masks (67MB) + embeddings (134MB) exactly once.
// ---------------------------------------------------------------------------
__global__ __launch_bounds__(256, 2)
void means_kernel(const float* __restrict__ emb, const float* __restrict__ masks) {
    const int blk   = blockIdx.x;
    const int b     = blk >> 5;
    const int chunk = blk & 31;
    const int base  = chunk * CHUNK;
    const int t     = threadIdx.x;
    const int w     = t >> 5, lane = t & 31;

    __shared__ int   slab[CHUNK];
    __shared__ int   scnt[8][Kn];

    // ---- Phase A: masks -> labels (float4, coalesced) + register counts ----
    const float* mb = masks + (size_t)b * Kn * HWn + base;
    int cnt[Kn];
    #pragma unroll
    for (int k = 0; k < Kn; k++) cnt[k] = 0;

    #pragma unroll
    for (int i = 0; i < CHUNK/(256*4); i++) {      // 2 iterations
        const int n = t*4 + i*1024;
        int l0 = 0, l1 = 0, l2 = 0, l3 = 0;
        #pragma unroll
        for (int k = 0; k < Kn; k++) {
            const float4 m = *(const float4*)(mb + (size_t)k*HWn + n);
            l0 += (m.x > 0.5f) ? k : 0;
            l1 += (m.y > 0.5f) ? k : 0;
            l2 += (m.z > 0.5f) ? k : 0;
            l3 += (m.w > 0.5f) ? k : 0;
        }
        slab[n+0] = l0; slab[n+1] = l1; slab[n+2] = l2; slab[n+3] = l3;
        #pragma unroll
        for (int k = 0; k < Kn; k++)
            cnt[k] += (l0==k) + (l1==k) + (l2==k) + (l3==k);
    }
    // warp-reduce counts, block-combine, write partial
    #pragma unroll
    for (int k = 0; k < Kn; k++) {
        int c = cnt[k];
        #pragma unroll
        for (int off = 16; off > 0; off >>= 1)
            c += __shfl_xor_sync(0xffffffffu, c, off);
        if (lane == 0) scnt[w][k] = c;
    }
    __syncthreads();
    if (t < Kn) {
        int s = 0;
        #pragma unroll
        for (int ww = 0; ww < 8; ww++) s += scnt[ww][t];
        g_cnt[blk][t] = (float)s;
    }

    // ---- Phase B: warp w owns channels e = w + 8*j, j=0..7, paired (2j2,2j2+1)
    unsigned long long acc[32];                    // acc[j2*8+k] = {ch 2j2, ch 2j2+1}
    #pragma unroll
    for (int i = 0; i < 32; i++) acc[i] = 0ull;

    const float* eb = emb + (size_t)b * En * HWn + base;

    #pragma unroll 2
    for (int i = 0; i < CHUNK/32; i++) {           // 64 iterations
        const int n = lane + i*32;
        const int l = slab[n];
        unsigned long long oh2[Kn];
        #pragma unroll
        for (int k = 0; k < Kn; k++)
            oh2[k] = (l == k) ? 0x3f8000003f800000ull : 0ull;   // {1.f,1.f} or {0,0}
        float v[8];
        #pragma unroll
        for (int j = 0; j < 8; j++)
            v[j] = eb[(size_t)(w + 8*j)*HWn + n];  // 8 coalesced LDGs, MLP-8
        unsigned long long v2[4];
        #pragma unroll
        for (int j2 = 0; j2 < 4; j2++)
            v2[j2] = pack2(v[2*j2], v[2*j2+1]);
        #pragma unroll
        for (int j2 = 0; j2 < 4; j2++) {
            #pragma unroll
            for (int k = 0; k < Kn; k++)
                acc[j2*8 + k] = ffma2(v2[j2], oh2[k], acc[j2*8 + k]);
        }
    }

    // ---- warp reduce (64-bit shuffles = 2x SHFL each), lane0 writes partials
    #pragma unroll
    for (int j2 = 0; j2 < 4; j2++) {
        #pragma unroll
        for (int k = 0; k < Kn; k++) {
            float lo, hi;
            unpack2(acc[j2*8 + k], lo, hi);
            #pragma unroll
            for (int off = 16; off > 0; off >>= 1) {
                lo += __shfl_xor_sync(0xffffffffu, lo, off);
                hi += __shfl_xor_sync(0xffffffffu, hi, off);
            }
            if (lane == 0) {
                const int e0 = w + 16*j2;          // channel 2*j2  slot
                g_part[blk][k*En + e0    ] = lo;
                g_part[blk][k*En + e0 + 8] = hi;   // channel 2*j2+1 slot
            }
        }
    }
}

// ---------------------------------------------------------------------------
// Kernel 2: per-image contrastive loss. grid = 8 blocks, 256 threads.
// ---------------------------------------------------------------------------
__global__ __launch_bounds__(256)
void loss_kernel(const float* __restrict__ emb, const int* __restrict__ pos_pix) {
    const int b = blockIdx.x;
    const int t = threadIdx.x;

    __shared__ float mn[Kn][En];       // normalized class means
    __shared__ float cntk[Kn];
    __shared__ float inv_nrm[Kn];
    __shared__ float part[256][9];     // per (term,slice): zz + 8 dots

    // counts: sum 32 chunk partials
    if (t < Kn) {
        float c = 0.f;
        #pragma unroll
        for (int cch = 0; cch < NCHUNK; cch++) c += g_cnt[b*NCHUNK + cch][t];
        cntk[t] = fmaxf(c, 1.f);
    }
    __syncthreads();

    // means: sum 32 chunk partials per (k,e) -> divide by count
    #pragma unroll
    for (int i = 0; i < 2; i++) {
        const int idx = t + i*256;         // k*64 + e
        const int k = idx >> 6, e = idx & 63;
        float s = 0.f;
        #pragma unroll
        for (int cch = 0; cch < NCHUNK; cch++)
            s += g_part[b*NCHUNK + cch][idx];
        mn[k][e] = s / cntk[k];
    }
    __syncthreads();
    if (t < Kn) {
        float s = 0.f;
        #pragma unroll
        for (int e = 0; e < En; e++) { const float v = mn[t][e]; s = fmaf(v, v, s); }
        inv_nrm[t] = 1.f / fmaxf(sqrtf(s), EPSf);
    }
    __syncthreads();
    #pragma unroll
    for (int i = 0; i < 2; i++) {
        const int idx = t + i*256;
        mn[idx >> 6][idx & 63] *= inv_nrm[idx >> 6];
    }
    __syncthreads();

    // 32 terms (k,s) x 8 e-slices -> 256 threads
    const int term  = t >> 3;          // 0..31
    const int slice = t & 7;
    const int k = term >> 2, s = term & 3;
    const int pix = pos_pix[(b*Kn + k)*NPOSn + s];
    const float* eb = emb + (size_t)b * En * HWn + pix;

    float zz = 0.f, dot[Kn];
    #pragma unroll
    for (int c = 0; c < Kn; c++) dot[c] = 0.f;
    #pragma unroll
    for (int ee = 0; ee < 8; ee++) {
        const int e = slice*8 + ee;
        const float z = eb[(size_t)e * HWn];
        zz = fmaf(z, z, zz);
        #pragma unroll
        for (int c = 0; c < Kn; c++) dot[c] = fmaf(z, mn[c][e], dot[c]);
    }
    part[t][0] = zz;
    #pragma unroll
    for (int c = 0; c < Kn; c++) part[t][c+1] = dot[c];
    __syncthreads();

    if (t < 32) {
        float zzt = 0.f, d[Kn];
        #pragma unroll
        for (int c = 0; c < Kn; c++) d[c] = 0.f;
        #pragma unroll
        for (int sl = 0; sl < 8; sl++) {
            const int idx = t*8 + sl;
            zzt += part[idx][0];
            #pragma unroll
            for (int c = 0; c < Kn; c++) d[c] += part[idx][c+1];
        }
        const int kk = t >> 2;
        const float inv = 1.f / fmaxf(sqrtf(zzt), EPSf);
        float sims[Kn], mx = -1e30f;
        #pragma unroll
        for (int c = 0; c < Kn; c++) {
            sims[c] = d[c] * inv * (1.f / TEMPf);
            mx = fmaxf(mx, sims[c]);
        }
        float se = 0.f;
        #pragma unroll
        for (int c = 0; c < Kn; c++) se += expf(sims[c] - mx);
        float loss = (mx + logf(se)) - sims[kk];
        #pragma unroll
        for (int off = 16; off > 0; off >>= 1)
            loss += __shfl_xor_sync(0xffffffffu, loss, off);
        if (t == 0) g_partial[b] = loss;
    }
}

// ---------------------------------------------------------------------------
// Kernel 3: deterministic final sum -> scalar
// (0.5*(l1+l2)).mean() over [P,K,S] = sum of all B*K*S term losses / 256
// ---------------------------------------------------------------------------
__global__ void final_kernel(float* __restrict__ out) {
    float s = 0.f;
    #pragma unroll
    for (int i = 0; i < Bn; i++) s += g_partial[i];
    out[0] = s * (1.f / 256.f);
}

// ---------------------------------------------------------------------------
extern "C" void kernel_launch(void* const* d_in, const int* in_sizes, int n_in,
                              void* d_out, int out_size) {
    const float* emb   = (const float*)d_in[0];   // [8,64,256,256] f32
    const float* masks = (const float*)d_in[1];   // [8,8,256,256]  f32
    const int*   pos   = (const int*)d_in[2];     // [8,8,4]        i32
    float* out = (float*)d_out;

    means_kernel<<<NBLK, 256>>>(emb, masks);
    loss_kernel<<<Bn, 256>>>(emb, pos);
    final_kernel<<<1, 1>>>(out);
}

// round 6
// speedup vs baseline: 1.0934x; 1.0934x over previous
#include <cuda_runtime.h>
#include <math.h>

// Problem constants
#define Bn    8
#define En    64
#define Hn    256
#define Wn    256
#define Kn    8
#define NPOSn 4
#define HWn   (Hn*Wn)
#define CHUNK 2048
#define NCHUNK (HWn/CHUNK)        // 32 chunks per image
#define NBLK  (Bn*NCHUNK)         // 256 means-blocks
#define TEMPf 0.2f
#define EPSf  1e-8f

// Allocation-free scratch (__device__ globals, zero-init at module load)
__device__ float g_part[NBLK][Kn*En];   // per-block partial class sums
__device__ float g_cnt[NBLK][Kn];       // per-block partial counts
__device__ float g_loss[Bn*Kn];         // per-(b,k) loss partials
__device__ unsigned int g_done;         // last-block-done counter (self-resetting)

// ---------------------------------------------------------------------------
// packed f32x2 helpers (sm_103a)
// ---------------------------------------------------------------------------
__device__ __forceinline__ unsigned long long ffma2(unsigned long long a,
                                                    unsigned long long b,
                                                    unsigned long long c) {
    unsigned long long d;
    asm("fma.rn.f32x2 %0, %1, %2, %3;" : "=l"(d) : "l"(a), "l"(b), "l"(c));
    return d;
}
__device__ __forceinline__ unsigned long long pack2(float lo, float hi) {
    unsigned long long r;
    asm("mov.b64 %0, {%1, %2};" : "=l"(r) : "f"(lo), "f"(hi));
    return r;
}
__device__ __forceinline__ void unpack2(unsigned long long v, float& lo, float& hi) {
    asm("mov.b64 {%0, %1}, %2;" : "=f"(lo), "=f"(hi) : "l"(v));
}

// ---------------------------------------------------------------------------
// Kernel 1: class-sum partials. grid = 256 (8 images x 32 chunks), 256 thr.
// Streams masks (67MB) + embeddings (134MB) exactly once. Target: DRAM-bound.
// ---------------------------------------------------------------------------
__global__ __launch_bounds__(256, 2)
void means_kernel(const float* __restrict__ emb, const float* __restrict__ masks) {
    const int blk   = blockIdx.x;
    const int b     = blk >> 5;
    const int chunk = blk & 31;
    const int base  = chunk * CHUNK;
    const int t     = threadIdx.x;
    const int w     = t >> 5, lane = t & 31;

    __shared__ int slab[CHUNK];
    __shared__ int scnt[8][Kn];

    // ---- Phase A: masks -> labels (float4 streaming) + register counts ----
    const float* mb = masks + (size_t)b * Kn * HWn + base;
    int cnt[Kn];
    #pragma unroll
    for (int k = 0; k < Kn; k++) cnt[k] = 0;

    #pragma unroll
    for (int i = 0; i < CHUNK/(256*4); i++) {      // 2 iterations
        const int n = t*4 + i*1024;
        int l0 = 0, l1 = 0, l2 = 0, l3 = 0;
        #pragma unroll
        for (int k = 0; k < Kn; k++) {
            const float4 m = __ldcs((const float4*)(mb + (size_t)k*HWn + n));
            l0 += (m.x > 0.5f) ? k : 0;
            l1 += (m.y > 0.5f) ? k : 0;
            l2 += (m.z > 0.5f) ? k : 0;
            l3 += (m.w > 0.5f) ? k : 0;
        }
        slab[n+0] = l0; slab[n+1] = l1; slab[n+2] = l2; slab[n+3] = l3;
        #pragma unroll
        for (int k = 0; k < Kn; k++)
            cnt[k] += (l0==k) + (l1==k) + (l2==k) + (l3==k);
    }
    #pragma unroll
    for (int k = 0; k < Kn; k++) {
        int c = cnt[k];
        #pragma unroll
        for (int off = 16; off > 0; off >>= 1)
            c += __shfl_xor_sync(0xffffffffu, c, off);
        if (lane == 0) scnt[w][k] = c;
    }
    __syncthreads();
    if (t < Kn) {
        int s = 0;
        #pragma unroll
        for (int ww = 0; ww < 8; ww++) s += scnt[ww][t];
        g_cnt[blk][t] = (float)s;
    }

    // ---- Phase B: warp w owns channels e = w + 8*j. 4-pixel quads (float4),
    //      channels in two half-batches of 4 LDG.128 (16 lines in flight) ----
    unsigned long long acc[32];            // acc[j2*8+k] = {ch pair}
    #pragma unroll
    for (int i = 0; i < 32; i++) acc[i] = 0ull;

    const float* eb = emb + (size_t)b * En * HWn + base;

    for (int i = 0; i < CHUNK/128; i++) {          // 16 iterations
        const int n4 = (i*32 + lane)*4;
        const int4 L = *(const int4*)&slab[n4];
        const int lab[4] = {L.x, L.y, L.z, L.w};

        #pragma unroll
        for (int half = 0; half < 2; half++) {
            float4 v[4];
            #pragma unroll
            for (int jj = 0; jj < 4; jj++)
                v[jj] = __ldcs((const float4*)(eb + (size_t)(w + 8*(jj + 4*half))*HWn + n4));

            #pragma unroll
            for (int p = 0; p < 4; p++) {
                const int l = lab[p];
                unsigned long long oh2[Kn];
                #pragma unroll
                for (int k = 0; k < Kn; k++)
                    oh2[k] = (l == k) ? 0x3f8000003f800000ull : 0ull;
                const float* vp0 = (const float*)&v[0];
                const float* vp1 = (const float*)&v[1];
                const float* vp2 = (const float*)&v[2];
                const float* vp3 = (const float*)&v[3];
                const unsigned long long va = pack2(vp0[p], vp1[p]);   // chans w+8*(4h), w+8*(4h+1)
                const unsigned long long vb = pack2(vp2[p], vp3[p]);   // chans w+8*(4h+2), w+8*(4h+3)
                const int j2a = 2*half, j2b = 2*half + 1;
                #pragma unroll
                for (int k = 0; k < Kn; k++) {
                    acc[j2a*8 + k] = ffma2(va, oh2[k], acc[j2a*8 + k]);
                    acc[j2b*8 + k] = ffma2(vb, oh2[k], acc[j2b*8 + k]);
                }
            }
        }
    }

    // ---- warp reduce, lane0 writes partials ----
    // acc[j2*8+k] = {chan w+8*(2*j2), chan w+8*(2*j2+1)} summed over this warp's pixels
    #pragma unroll
    for (int j2 = 0; j2 < 4; j2++) {
        #pragma unroll
        for (int k = 0; k < Kn; k++) {
            float lo, hi;
            unpack2(acc[j2*8 + k], lo, hi);
            #pragma unroll
            for (int off = 16; off > 0; off >>= 1) {
                lo += __shfl_xor_sync(0xffffffffu, lo, off);
                hi += __shfl_xor_sync(0xffffffffu, hi, off);
            }
            if (lane == 0) {
                const int e0 = w + 8*(2*j2);
                g_part[blk][k*En + e0    ] = lo;
                g_part[blk][k*En + e0 + 8] = hi;
            }
        }
    }
}

// ---------------------------------------------------------------------------
// Kernel 2: loss + fused final. grid = 64 blocks (b,k), 256 threads.
// Last block (atomic counter) sums all partials in fixed order -> scalar out.
// ---------------------------------------------------------------------------
__global__ __launch_bounds__(256)
void loss_kernel(const float* __restrict__ emb, const int* __restrict__ pos_pix,
                 float* __restrict__ out) {
    const int blk = blockIdx.x;
    const int b = blk >> 3, k = blk & 7;
    const int t = threadIdx.x;

    __shared__ float mn[Kn][En];       // normalized class means of image b
    __shared__ float cntk[Kn];
    __shared__ float inv_nrm[Kn];
    __shared__ float tl[4];            // per-term losses

    if (t < Kn) {
        float c = 0.f;
        #pragma unroll
        for (int cc = 0; cc < NCHUNK; cc++) c += g_cnt[b*NCHUNK + cc][t];
        cntk[t] = fmaxf(c, 1.f);
    }
    __syncthreads();

    #pragma unroll
    for (int i = 0; i < 2; i++) {
        const int idx = t + i*256;                 // k'*64 + e
        float s = 0.f;
        #pragma unroll
        for (int cc = 0; cc < NCHUNK; cc++)
            s += g_part[b*NCHUNK + cc][idx];
        mn[idx >> 6][idx & 63] = s / cntk[idx >> 6];
    }
    __syncthreads();
    if (t < Kn) {
        float s = 0.f;
        #pragma unroll
        for (int e = 0; e < En; e++) { const float v = mn[t][e]; s = fmaf(v, v, s); }
        inv_nrm[t] = 1.f / fmaxf(sqrtf(s), EPSf);
    }
    __syncthreads();
    #pragma unroll
    for (int i = 0; i < 2; i++) {
        const int idx = t + i*256;
        mn[idx >> 6][idx & 63] *= inv_nrm[idx >> 6];
    }
    __syncthreads();

    // 4 terms (s) x 1 warp each; lane covers channels e=lane, e=lane+32
    if (t < 128) {
        const int s    = t >> 5;
        const int lane = t & 31;
        const int pix  = pos_pix[(b*Kn + k)*NPOSn + s];
        const float* eb = emb + (size_t)b * En * HWn + pix;
        const float z0 = eb[(size_t)lane * HWn];
        const float z1 = eb[(size_t)(lane + 32) * HWn];

        float zz = z0*z0 + z1*z1;
        float dot[Kn];
        #pragma unroll
        for (int c = 0; c < Kn; c++)
            dot[c] = z0*mn[c][lane] + z1*mn[c][lane + 32];

        #pragma unroll
        for (int off = 16; off > 0; off >>= 1) {
            zz += __shfl_xor_sync(0xffffffffu, zz, off);
            #pragma unroll
            for (int c = 0; c < Kn; c++)
                dot[c] += __shfl_xor_sync(0xffffffffu, dot[c], off);
        }
        if (lane == 0) {
            const float inv = 1.f / fmaxf(sqrtf(zz), EPSf);
            float sims[Kn], mx = -1e30f;
            #pragma unroll
            for (int c = 0; c < Kn; c++) {
                sims[c] = dot[c] * inv * (1.f / TEMPf);
                mx = fmaxf(mx, sims[c]);
            }
            float se = 0.f;
            #pragma unroll
            for (int c = 0; c < Kn; c++) se += expf(sims[c] - mx);
            tl[s] = (mx + logf(se)) - sims[k];
        }
    }
    __syncthreads();

    if (t == 0) {
        g_loss[blk] = tl[0] + tl[1] + tl[2] + tl[3];
        __threadfence();
        if (atomicAdd(&g_done, 1u) == (unsigned)(Bn*Kn - 1)) {
            float s = 0.f;
            #pragma unroll
            for (int i = 0; i < Bn*Kn; i++) s += __ldcg(&g_loss[i]);  // fixed order
            out[0] = s * (1.f / 256.f);   // mean over [P,K,S] of 0.5*(l1+l2)
            g_done = 0;                   // reset for next graph replay
            __threadfence();
        }
    }
}

// ---------------------------------------------------------------------------
extern "C" void kernel_launch(void* const* d_in, const int* in_sizes, int n_in,
                              void* d_out, int out_size) {
    const float* emb   = (const float*)d_in[0];   // [8,64,256,256] f32
    const float* masks = (const float*)d_in[1];   // [8,8,256,256]  f32
    const int*   pos   = (const int*)d_in[2];     // [8,8,4]        i32
    float* out = (float*)d_out;

    means_kernel<<<NBLK, 256>>>(emb, masks);
    loss_kernel<<<Bn*Kn, 256>>>(emb, pos, out);
}